// round 15
// baseline (speedup 1.0000x reference)
#include <cuda_runtime.h>
#include <cuda_fp16.h>

// Problem constants (shapes fixed by the dataset)
#define UQ 100000          // users
#define MQ 50000           // movies
#define HH 64              // hidden dim
#define UN (UQ*HH)
#define MN (MQ*HH)
#define PAD_U 64           // max user degree slots (Poisson(20) tail safe)
#define PAD_M 128          // max movie degree slots (Poisson(40) tail safe)

// Scratch layout inside one big __device__ buffer (offsets in floats)
#define OFF_XU0  0
#define OFF_XU1  (OFF_XU0 + UN)
#define OFF_XM0  (OFF_XU1 + UN)
#define OFF_XM1  (OFF_XM0 + MN)
#define OFF_ZU   (OFF_XM1 + MN)      // z_u = x_u @ Wr^T + b   [U,64] fp32
#define OFF_ZM   (OFF_ZU + UN)       // z_m = x_m @ Wr^T + b   [M,64] fp32
#define TOTAL_F  (OFF_ZM + MN)

__device__ __align__(16) float g_buf[TOTAL_F];        // ~115 MB scratch
__device__ int g_deg[UQ + MQ];                        // users then movies (fill cursors)
__device__ __align__(16) int g_bucket_u[UQ * PAD_U];  // movie ids per user
__device__ __align__(16) int g_bucket_m[MQ * PAD_M];  // user ids per movie
__device__ __align__(16) __half g_hyu[UN];            // y_u = x_u @ Wl[l,0]^T (fp16)
__device__ __align__(16) __half g_hym[MN];            // y_m = x_m @ Wl[l,1]^T (fp16)

// ---------------------------------------------------------------------------
// Packed f32x2 helpers (Blackwell sm_103a FFMA2 path)
__device__ __forceinline__ unsigned long long pack_dup(float x) {
    unsigned long long r;
    asm("mov.b64 %0, {%1, %1};" : "=l"(r) : "f"(x));
    return r;
}
__device__ __forceinline__ unsigned long long pack2(float a, float b) {
    unsigned long long r;
    asm("mov.b64 %0, {%1, %2};" : "=l"(r) : "f"(a), "f"(b));
    return r;
}
__device__ __forceinline__ void ffma2(unsigned long long& d,
                                      unsigned long long a, unsigned long long b) {
    asm("fma.rn.f32x2 %0, %1, %2, %0;" : "+l"(d) : "l"(a), "l"(b));
}
__device__ __forceinline__ float2 unpack2(unsigned long long v) {
    float2 f;
    asm("mov.b64 {%0, %1}, %2;" : "=f"(f.x), "=f"(f.y) : "l"(v));
    return f;
}

// ---------------------------------------------------------------------------
// Fused init: movie blocks project movie_x; user blocks copy user_emb;
// tail blocks zero the degree counters (no ordering hazard: k_fill runs after).
__global__ void __launch_bounds__(256)
k_init(const float4* __restrict__ uemb,
       const float* __restrict__ mx, const float* __restrict__ w,
       const float* __restrict__ b, const float* __restrict__ memb,
       int MB4, int UBc, int M, int U) {
    int tid = threadIdx.x;
    if ((int)blockIdx.x < MB4) {
        __shared__ float xs[4][20];
        int r = tid >> 6, o = tid & 63;
        int row = blockIdx.x * 4 + r;
        if (tid < 80) {
            int rr = tid / 20, cc = tid % 20;
            int g = blockIdx.x * 4 + rr;
            if (g < M) xs[rr][cc] = __ldg(mx + g * 20 + cc);
        }
        __syncthreads();
        if (row < M) {
            float acc = __ldg(b + o) + __ldg(memb + row * 64 + o);
#pragma unroll
            for (int k = 0; k < 20; k++) acc = fmaf(xs[r][k], __ldg(w + o * 20 + k), acc);
            g_buf[OFF_XM0 + row * 64 + o] = acc;
        }
    } else if ((int)blockIdx.x < MB4 + UBc) {
        int i = ((int)blockIdx.x - MB4) * 256 + tid;
        if (i < U * 16) ((float4*)(g_buf + OFF_XU0))[i] = __ldg(uemb + i);
    } else {
        int i = ((int)blockIdx.x - MB4 - UBc) * 256 + tid;
        if (i < U + M) g_deg[i] = 0;
    }
}

// Bucket fill: degree counting and slot allocation in one pass over edges.
__global__ void k_fill(const int* __restrict__ es, const int* __restrict__ ed, int E) {
    int e = blockIdx.x * blockDim.x + threadIdx.x;
    if (e >= E) return;
    int u = __ldg(es + e), m = __ldg(ed + e);
    int su = atomicAdd(&g_deg[u], 1);
    if (su < PAD_U) g_bucket_u[u * PAD_U + su] = m;
    int sm = atomicAdd(&g_deg[UQ + m], 1);
    if (sm < PAD_M) g_bucket_m[m * PAD_M + sm] = u;
}

// ---------------------------------------------------------------------------
// Pre-transform: y = x @ Wl_y^T (fp16 out), z = x @ Wr_z^T + b (fp32).
// Persistent tiles; thread = 2 rows x 4 outs. Grid = 5 blocks/SM exactly
// (regs=50 cap), split work-proportional movie:user = 1:2.
#define PROWS 32
#define WPAD 68            // fp32 row stride (floats)
#define WPADH 68           // fp16 weight row stride (halves)
#define GM_BLOCKS 246      // movie-segment blocks
#define GU_BLOCKS 494      // user-segment blocks (total 740 = 148*5)
__global__ void __launch_bounds__(256)
k_pre(int xm_off, int xu_off, const float* __restrict__ wl,
      const float* __restrict__ bl, const float* __restrict__ wr,
      int layer, int M, int U) {
    __shared__ __half wsy[64 * WPADH];    // Wl_y transposed [i][o], fp16
    __shared__ float  wsz[64 * WPAD];     // Wr_z transposed [i][o], fp32
    __shared__ float  rs[PROWS * WPAD];   // x rows
    const bool is_movie = (int)blockIdx.x < GM_BLOCKS;
    const int et_y = is_movie ? 1 : 0;    // movie y feeds user-dst edges
    const int et_z = is_movie ? 0 : 1;
    const float* wly = wl + (layer * 2 + et_y) * 4096;
    const float* wrz = wr + (layer * 2 + et_z) * 4096;
    const float* blz = bl + (layer * 2 + et_z) * 64;
    const int nrows = is_movie ? M : U;
    const int x_off = is_movie ? xm_off : xu_off;
    const int z_off = is_movie ? OFF_ZM : OFF_ZU;
    __half* ytab    = is_movie ? g_hym : g_hyu;
    const int ntiles = (nrows + PROWS - 1) / PROWS;
    const int t0     = is_movie ? blockIdx.x : blockIdx.x - GM_BLOCKS;
    const int tstep  = is_movie ? GM_BLOCKS : GU_BLOCKS;
    int tid = threadIdx.x;

    // Load weights ONCE per block.
    for (int idx = tid; idx < 4096; idx += 256) {
        int o = idx >> 6, i = idx & 63;   // coalesced global read
        wsy[i * WPADH + o] = __float2half_rn(__ldg(wly + idx));
        wsz[i * WPAD + o]  = __ldg(wrz + idx);
    }
    int og = tid & 15, rg = tid >> 4;     // 16 o-groups x 16 row-groups
    int o0 = og * 4, r0 = rg * 2;
    float4 bz = *(const float4*)(blz + o0);
    const unsigned long long zb_a = pack2(bz.x, bz.y), zb_b = pack2(bz.z, bz.w);
    const float4* x4 = (const float4*)(g_buf + x_off);
    float* z = g_buf + z_off;
    int ldr = tid >> 4, ldq = tid & 15;
    __syncthreads();

    for (int t = t0; t < ntiles; t += tstep) {
        const int row0 = t * PROWS;
#pragma unroll
        for (int rr = ldr; rr < PROWS; rr += 16) {
            int g = row0 + rr;
            if (g < nrows) *(float4*)&rs[rr * WPAD + ldq * 4] = __ldg(x4 + g * 16 + ldq);
        }
        __syncthreads();

        unsigned long long y0a = 0ull, y0b = 0ull, y1a = 0ull, y1b = 0ull;
        unsigned long long z0a = zb_a, z0b = zb_b, z1a = zb_a, z1b = zb_b;
#pragma unroll 16
        for (int i = 0; i < 64; i++) {
            uint2 wyh = *(const uint2*)&wsy[i * WPADH + o0];           // 4 halves, LDS.64
            ulonglong2 wz = *(const ulonglong2*)&wsz[i * WPAD + o0];   // 4 floats, LDS.128
            float2 wy01 = __half22float2(*(__half2*)&wyh.x);
            float2 wy23 = __half22float2(*(__half2*)&wyh.y);
            unsigned long long wya = pack2(wy01.x, wy01.y);
            unsigned long long wyb = pack2(wy23.x, wy23.y);
            unsigned long long px0 = pack_dup(rs[r0 * WPAD + i]);
            unsigned long long px1 = pack_dup(rs[(r0 + 1) * WPAD + i]);
            ffma2(y0a, px0, wya); ffma2(y0b, px0, wyb);
            ffma2(z0a, px0, wz.x); ffma2(z0b, px0, wz.y);
            ffma2(y1a, px1, wya); ffma2(y1b, px1, wyb);
            ffma2(z1a, px1, wz.x); ffma2(z1b, px1, wz.y);
        }
        float2 y0xy = unpack2(y0a), y0zw = unpack2(y0b);
        float2 y1xy = unpack2(y1a), y1zw = unpack2(y1b);
        float2 z0xy = unpack2(z0a), z0zw = unpack2(z0b);
        float2 z1xy = unpack2(z1a), z1zw = unpack2(z1b);

        int g0 = row0 + r0;
        if (g0 < nrows) {
            *(float4*)(z + g0 * 64 + o0) = make_float4(z0xy.x, z0xy.y, z0zw.x, z0zw.y);
            uint2 p;
            ((__half2*)&p)[0] = __floats2half2_rn(y0xy.x, y0xy.y);
            ((__half2*)&p)[1] = __floats2half2_rn(y0zw.x, y0zw.y);
            *(uint2*)(ytab + g0 * 64 + o0) = p;
        }
        if (g0 + 1 < nrows) {
            *(float4*)(z + (g0 + 1) * 64 + o0) = make_float4(z1xy.x, z1xy.y, z1zw.x, z1zw.y);
            uint2 p;
            ((__half2*)&p)[0] = __floats2half2_rn(y1xy.x, y1xy.y);
            ((__half2*)&p)[1] = __floats2half2_rn(y1zw.x, y1zw.y);
            *(uint2*)(ytab + (g0 + 1) * 64 + o0) = p;
        }
        __syncthreads();   // rs reused next tile
    }
}

// ---------------------------------------------------------------------------
__device__ __forceinline__ void acc8(float* a, uint4 v) {
    float2 f;
    f = __half22float2(*(__half2*)&v.x); a[0] += f.x; a[1] += f.y;
    f = __half22float2(*(__half2*)&v.y); a[2] += f.x; a[3] += f.y;
    f = __half22float2(*(__half2*)&v.z); a[4] += f.x; a[5] += f.y;
    f = __half22float2(*(__half2*)&v.w); a[6] += f.x; a[7] += f.y;
}
// Pairwise fp16 add of two neighbor row fragments (4 HADD2).
__device__ __forceinline__ uint4 hadd4(uint4 a, uint4 b) {
    uint4 r;
    *(__half2*)&r.x = __hadd2(*(const __half2*)&a.x, *(const __half2*)&b.x);
    *(__half2*)&r.y = __hadd2(*(const __half2*)&a.y, *(const __half2*)&b.y);
    *(__half2*)&r.z = __hadd2(*(const __half2*)&a.z, *(const __half2*)&b.z);
    *(__half2*)&r.w = __hadd2(*(const __half2*)&a.w, *(const __half2*)&b.w);
    return r;
}
__device__ __forceinline__ void proc8(float* a, const uint4* __restrict__ y4,
                                      int4 na, int4 nb, int lane) {
    uint4 v0 = __ldg(y4 + na.x * 8 + lane);
    uint4 v1 = __ldg(y4 + na.y * 8 + lane);
    uint4 v2 = __ldg(y4 + na.z * 8 + lane);
    uint4 v3 = __ldg(y4 + na.w * 8 + lane);
    uint4 v4 = __ldg(y4 + nb.x * 8 + lane);
    uint4 v5 = __ldg(y4 + nb.y * 8 + lane);
    uint4 v6 = __ldg(y4 + nb.z * 8 + lane);
    uint4 v7 = __ldg(y4 + nb.w * 8 + lane);
    acc8(a, hadd4(v0, v1)); acc8(a, hadd4(v2, v3));
    acc8(a, hadd4(v4, v5)); acc8(a, hadd4(v6, v7));
}

// Gather-mean of fp16 y rows + z + optional relu -> x_new (fp32).
// 8 lanes per node, 8 rows/iter, SOFTWARE-PIPELINED index prefetch: the
// next iteration's indices load while the current rows are in flight,
// removing one L2 round-trip from the per-iteration critical path.
__global__ void __launch_bounds__(256, 6)
k_gather_add(int xm_out, int xu_out, int M, int U, int do_relu) {
    int t = blockIdx.x * blockDim.x + threadIdx.x;
    int node = t >> 3;
    if (node >= M + U) return;
    int lane = t & 7;
    bool is_movie = node < M;
    int local = is_movie ? node : node - M;
    const int pad = is_movie ? PAD_M : PAD_U;
    const int* bk = (is_movie ? g_bucket_m : g_bucket_u) + (long)local * pad;
    int dt = g_deg[(is_movie ? UQ : 0) + local];
    float iv = 1.f / fmaxf((float)dt, 1.f);
    int d = min(dt, pad);
    const uint4* y4 = (const uint4*)(is_movie ? g_hyu : g_hym);  // gather OTHER side's y

    float a[8] = {0.f, 0.f, 0.f, 0.f, 0.f, 0.f, 0.f, 0.f};
    int i = 0;
    if (d >= 8) {
        int4 na = __ldg((const int4*)(bk));
        int4 nb = __ldg((const int4*)(bk + 4));
        for (; i + 16 <= d; i += 8) {
            int4 pa = __ldg((const int4*)(bk + i + 8));    // prefetch next chunk
            int4 pb = __ldg((const int4*)(bk + i + 12));
            proc8(a, y4, na, nb, lane);
            na = pa; nb = pb;
        }
        proc8(a, y4, na, nb, lane);                        // drain pipelined chunk
        i += 8;
    }
    for (; i + 4 <= d; i += 4) {
        int4 na = __ldg((const int4*)(bk + i));
        uint4 v0 = __ldg(y4 + na.x * 8 + lane);
        uint4 v1 = __ldg(y4 + na.y * 8 + lane);
        uint4 v2 = __ldg(y4 + na.z * 8 + lane);
        uint4 v3 = __ldg(y4 + na.w * 8 + lane);
        acc8(a, hadd4(v0, v1)); acc8(a, hadd4(v2, v3));
    }
    for (; i < d; i++) {
        int nb = __ldg(bk + i);
        acc8(a, __ldg(y4 + nb * 8 + lane));
    }
    const float4* zp = (const float4*)(g_buf + (is_movie ? OFF_ZM : OFF_ZU)) + local * 16 + lane * 2;
    float4 z0 = __ldg(zp), z1 = __ldg(zp + 1);
    float4 r0 = make_float4(fmaf(a[0], iv, z0.x), fmaf(a[1], iv, z0.y),
                            fmaf(a[2], iv, z0.z), fmaf(a[3], iv, z0.w));
    float4 r1 = make_float4(fmaf(a[4], iv, z1.x), fmaf(a[5], iv, z1.y),
                            fmaf(a[6], iv, z1.z), fmaf(a[7], iv, z1.w));
    if (do_relu) {
        r0.x = fmaxf(r0.x, 0.f); r0.y = fmaxf(r0.y, 0.f);
        r0.z = fmaxf(r0.z, 0.f); r0.w = fmaxf(r0.w, 0.f);
        r1.x = fmaxf(r1.x, 0.f); r1.y = fmaxf(r1.y, 0.f);
        r1.z = fmaxf(r1.z, 0.f); r1.w = fmaxf(r1.w, 0.f);
    }
    float4* o4 = (float4*)(g_buf + (is_movie ? xm_out : xu_out)) + local * 16 + lane * 2;
    o4[0] = r0;
    o4[1] = r1;
}

// out[l] = dot(x_u[label_src[l]], x_m[label_dst[l]]); 8 lanes per label.
__global__ void k_labels(const int* __restrict__ ls, const int* __restrict__ ld,
                         int xu_off, int xm_off, float* __restrict__ out, int L) {
    int t = blockIdx.x * blockDim.x + threadIdx.x;
    int l = t >> 3;
    if (l >= L) return;
    int lane = t & 7;
    const float4* xu = (const float4*)(g_buf + xu_off);
    const float4* xm = (const float4*)(g_buf + xm_off);
    int s = __ldg(ls + l), d = __ldg(ld + l);
    float4 a0 = __ldg(xu + s * 16 + lane * 2);
    float4 a1 = __ldg(xu + s * 16 + lane * 2 + 1);
    float4 b0 = __ldg(xm + d * 16 + lane * 2);
    float4 b1 = __ldg(xm + d * 16 + lane * 2 + 1);
    float v = a0.x * b0.x;
    v = fmaf(a0.y, b0.y, v); v = fmaf(a0.z, b0.z, v); v = fmaf(a0.w, b0.w, v);
    v = fmaf(a1.x, b1.x, v); v = fmaf(a1.y, b1.y, v);
    v = fmaf(a1.z, b1.z, v); v = fmaf(a1.w, b1.w, v);
    v += __shfl_xor_sync(0xffffffffu, v, 4);
    v += __shfl_xor_sync(0xffffffffu, v, 2);
    v += __shfl_xor_sync(0xffffffffu, v, 1);
    if (lane == 0) out[l] = v;
}

// ---------------------------------------------------------------------------
extern "C" void kernel_launch(void* const* d_in, const int* in_sizes, int n_in,
                              void* d_out, int out_size) {
    const float* movie_x   = (const float*)d_in[0];
    const float* user_emb  = (const float*)d_in[1];
    const float* movie_emb = (const float*)d_in[2];
    const float* mw        = (const float*)d_in[3];
    const float* mb        = (const float*)d_in[4];
    const float* wl        = (const float*)d_in[5];
    const float* blb       = (const float*)d_in[6];
    const float* wr        = (const float*)d_in[7];
    const int*   es        = (const int*)d_in[8];
    const int*   ed        = (const int*)d_in[9];
    const int*   ls        = (const int*)d_in[10];
    const int*   ld        = (const int*)d_in[11];
    float* out = (float*)d_out;

    const int U = in_sizes[1] / HH;
    const int M = in_sizes[2] / HH;
    const int E = in_sizes[8];
    const int L = in_sizes[10];
    const int TB = 256;

    // launch 1: fused feature init (movies projected, users copied, deg zeroed)
    const int MB4 = (M + 3) / 4;
    const int UBc = (U * 16 + TB - 1) / TB;
    const int ZB  = (U + M + TB - 1) / TB;
    k_init<<<MB4 + UBc + ZB, TB>>>((const float4*)user_emb, movie_x, mw, mb, movie_emb,
                                   MB4, UBc, M, U);
    // launch 2: adjacency buckets (+degree counting)
    k_fill<<<(E + TB - 1) / TB, TB>>>(es, ed, E);

    const int GAB = (int)(((long)(M + U) * 8 + TB - 1) / TB);
    for (int layer = 0; layer < 2; layer++) {
        const int xu_in  = layer ? OFF_XU1 : OFF_XU0;
        const int xm_in  = layer ? OFF_XM1 : OFF_XM0;
        const int xu_out = layer ? OFF_XU0 : OFF_XU1;
        const int xm_out = layer ? OFF_XM0 : OFF_XM1;

        // launch 3/5: dense pre-transform y,z (persistent tiles, 5 blocks/SM)
        k_pre<<<GM_BLOCKS + GU_BLOCKS, 256>>>(xm_in, xu_in, wl, blb, wr, layer, M, U);
        // launch 4/6: gather-mean(y) + z (+relu) — profiled slot
        k_gather_add<<<GAB, TB>>>(xm_out, xu_out, M, U, layer == 0);
    }

    // final features are in the *0 buffers
    long lt = (long)L * 8;
    k_labels<<<(int)((lt + TB - 1) / TB), TB>>>(ls, ld, OFF_XU0, OFF_XM0, out, L);
}

// round 16
// speedup vs baseline: 1.0551x; 1.0551x over previous
#include <cuda_runtime.h>
#include <cuda_fp16.h>

// Problem constants (shapes fixed by the dataset)
#define UQ 100000          // users
#define MQ 50000           // movies
#define HH 64              // hidden dim
#define UN (UQ*HH)
#define MN (MQ*HH)
#define PAD_U 64           // max user degree slots (Poisson(20) tail safe)
#define PAD_M 128          // max movie degree slots (Poisson(40) tail safe)

// Scratch layout inside one big __device__ buffer (offsets in floats)
#define OFF_XU0  0
#define OFF_XU1  (OFF_XU0 + UN)
#define OFF_XM0  (OFF_XU1 + UN)
#define OFF_XM1  (OFF_XM0 + MN)
#define OFF_ZU   (OFF_XM1 + MN)      // z_u = x_u @ Wr^T + b   [U,64] fp32
#define OFF_ZM   (OFF_ZU + UN)       // z_m = x_m @ Wr^T + b   [M,64] fp32
#define TOTAL_F  (OFF_ZM + MN)

__device__ __align__(16) float g_buf[TOTAL_F];        // ~115 MB scratch
__device__ int g_deg[UQ + MQ];                        // users then movies (fill cursors)
__device__ __align__(16) int g_bucket_u[UQ * PAD_U];  // movie ids per user
__device__ __align__(16) int g_bucket_m[MQ * PAD_M];  // user ids per movie
__device__ __align__(16) __half g_hyu[UN];            // y_u = x_u @ Wl[l,0]^T (fp16)
__device__ __align__(16) __half g_hym[MN];            // y_m = x_m @ Wl[l,1]^T (fp16)

// ---------------------------------------------------------------------------
// Packed f32x2 helpers (Blackwell sm_103a FFMA2 path)
__device__ __forceinline__ unsigned long long pack_dup(float x) {
    unsigned long long r;
    asm("mov.b64 %0, {%1, %1};" : "=l"(r) : "f"(x));
    return r;
}
__device__ __forceinline__ unsigned long long pack2(float a, float b) {
    unsigned long long r;
    asm("mov.b64 %0, {%1, %2};" : "=l"(r) : "f"(a), "f"(b));
    return r;
}
__device__ __forceinline__ void ffma2(unsigned long long& d,
                                      unsigned long long a, unsigned long long b) {
    asm("fma.rn.f32x2 %0, %1, %2, %0;" : "+l"(d) : "l"(a), "l"(b));
}
__device__ __forceinline__ float2 unpack2(unsigned long long v) {
    float2 f;
    asm("mov.b64 {%0, %1}, %2;" : "=f"(f.x), "=f"(f.y) : "l"(v));
    return f;
}

// ---------------------------------------------------------------------------
// Fused init: movie blocks project movie_x; user blocks copy user_emb;
// tail blocks zero the degree counters (no ordering hazard: k_fill runs after).
__global__ void __launch_bounds__(256)
k_init(const float4* __restrict__ uemb,
       const float* __restrict__ mx, const float* __restrict__ w,
       const float* __restrict__ b, const float* __restrict__ memb,
       int MB4, int UBc, int M, int U) {
    int tid = threadIdx.x;
    if ((int)blockIdx.x < MB4) {
        __shared__ float xs[4][20];
        int r = tid >> 6, o = tid & 63;
        int row = blockIdx.x * 4 + r;
        if (tid < 80) {
            int rr = tid / 20, cc = tid % 20;
            int g = blockIdx.x * 4 + rr;
            if (g < M) xs[rr][cc] = __ldg(mx + g * 20 + cc);
        }
        __syncthreads();
        if (row < M) {
            float acc = __ldg(b + o) + __ldg(memb + row * 64 + o);
#pragma unroll
            for (int k = 0; k < 20; k++) acc = fmaf(xs[r][k], __ldg(w + o * 20 + k), acc);
            g_buf[OFF_XM0 + row * 64 + o] = acc;
        }
    } else if ((int)blockIdx.x < MB4 + UBc) {
        int i = ((int)blockIdx.x - MB4) * 256 + tid;
        if (i < U * 16) ((float4*)(g_buf + OFF_XU0))[i] = __ldg(uemb + i);
    } else {
        int i = ((int)blockIdx.x - MB4 - UBc) * 256 + tid;
        if (i < U + M) g_deg[i] = 0;
    }
}

// Bucket fill: degree counting and slot allocation in one pass over edges.
__global__ void k_fill(const int* __restrict__ es, const int* __restrict__ ed, int E) {
    int e = blockIdx.x * blockDim.x + threadIdx.x;
    if (e >= E) return;
    int u = __ldg(es + e), m = __ldg(ed + e);
    int su = atomicAdd(&g_deg[u], 1);
    if (su < PAD_U) g_bucket_u[u * PAD_U + su] = m;
    int sm = atomicAdd(&g_deg[UQ + m], 1);
    if (sm < PAD_M) g_bucket_m[m * PAD_M + sm] = u;
}

// ---------------------------------------------------------------------------
// Pre-transform (round-14 PROVEN config): y = x @ Wl_y^T (fp16 out),
// z = x @ Wr_z^T + b (fp32). Persistent tiles; thread = 2 rows x 4 outs.
#define PROWS 32
#define WPAD 68            // fp32 row stride (floats)
#define WPADH 68           // fp16 weight row stride (halves)
#define GM_BLOCKS 296      // movie-segment blocks
#define GU_BLOCKS 592      // user-segment blocks
__global__ void __launch_bounds__(256)
k_pre(int xm_off, int xu_off, const float* __restrict__ wl,
      const float* __restrict__ bl, const float* __restrict__ wr,
      int layer, int M, int U) {
    __shared__ __half wsy[64 * WPADH];    // Wl_y transposed [i][o], fp16
    __shared__ float  wsz[64 * WPAD];     // Wr_z transposed [i][o], fp32
    __shared__ float  rs[PROWS * WPAD];   // x rows
    const bool is_movie = (int)blockIdx.x < GM_BLOCKS;
    const int et_y = is_movie ? 1 : 0;    // movie y feeds user-dst edges
    const int et_z = is_movie ? 0 : 1;
    const float* wly = wl + (layer * 2 + et_y) * 4096;
    const float* wrz = wr + (layer * 2 + et_z) * 4096;
    const float* blz = bl + (layer * 2 + et_z) * 64;
    const int nrows = is_movie ? M : U;
    const int x_off = is_movie ? xm_off : xu_off;
    const int z_off = is_movie ? OFF_ZM : OFF_ZU;
    __half* ytab    = is_movie ? g_hym : g_hyu;
    const int ntiles = (nrows + PROWS - 1) / PROWS;
    const int t0     = is_movie ? blockIdx.x : blockIdx.x - GM_BLOCKS;
    const int tstep  = is_movie ? GM_BLOCKS : GU_BLOCKS;
    int tid = threadIdx.x;

    // Load weights ONCE per block.
    for (int idx = tid; idx < 4096; idx += 256) {
        int o = idx >> 6, i = idx & 63;   // coalesced global read
        wsy[i * WPADH + o] = __float2half_rn(__ldg(wly + idx));
        wsz[i * WPAD + o]  = __ldg(wrz + idx);
    }
    int og = tid & 15, rg = tid >> 4;     // 16 o-groups x 16 row-groups
    int o0 = og * 4, r0 = rg * 2;
    float4 bz = *(const float4*)(blz + o0);
    const unsigned long long zb_a = pack2(bz.x, bz.y), zb_b = pack2(bz.z, bz.w);
    const float4* x4 = (const float4*)(g_buf + x_off);
    float* z = g_buf + z_off;
    int ldr = tid >> 4, ldq = tid & 15;
    __syncthreads();

    for (int t = t0; t < ntiles; t += tstep) {
        const int row0 = t * PROWS;
#pragma unroll
        for (int rr = ldr; rr < PROWS; rr += 16) {
            int g = row0 + rr;
            if (g < nrows) *(float4*)&rs[rr * WPAD + ldq * 4] = __ldg(x4 + g * 16 + ldq);
        }
        __syncthreads();

        unsigned long long y0a = 0ull, y0b = 0ull, y1a = 0ull, y1b = 0ull;
        unsigned long long z0a = zb_a, z0b = zb_b, z1a = zb_a, z1b = zb_b;
#pragma unroll 16
        for (int i = 0; i < 64; i++) {
            uint2 wyh = *(const uint2*)&wsy[i * WPADH + o0];           // 4 halves, LDS.64
            ulonglong2 wz = *(const ulonglong2*)&wsz[i * WPAD + o0];   // 4 floats, LDS.128
            float2 wy01 = __half22float2(*(__half2*)&wyh.x);
            float2 wy23 = __half22float2(*(__half2*)&wyh.y);
            unsigned long long wya = pack2(wy01.x, wy01.y);
            unsigned long long wyb = pack2(wy23.x, wy23.y);
            unsigned long long px0 = pack_dup(rs[r0 * WPAD + i]);
            unsigned long long px1 = pack_dup(rs[(r0 + 1) * WPAD + i]);
            ffma2(y0a, px0, wya); ffma2(y0b, px0, wyb);
            ffma2(z0a, px0, wz.x); ffma2(z0b, px0, wz.y);
            ffma2(y1a, px1, wya); ffma2(y1b, px1, wyb);
            ffma2(z1a, px1, wz.x); ffma2(z1b, px1, wz.y);
        }
        float2 y0xy = unpack2(y0a), y0zw = unpack2(y0b);
        float2 y1xy = unpack2(y1a), y1zw = unpack2(y1b);
        float2 z0xy = unpack2(z0a), z0zw = unpack2(z0b);
        float2 z1xy = unpack2(z1a), z1zw = unpack2(z1b);

        int g0 = row0 + r0;
        if (g0 < nrows) {
            *(float4*)(z + g0 * 64 + o0) = make_float4(z0xy.x, z0xy.y, z0zw.x, z0zw.y);
            uint2 p;
            ((__half2*)&p)[0] = __floats2half2_rn(y0xy.x, y0xy.y);
            ((__half2*)&p)[1] = __floats2half2_rn(y0zw.x, y0zw.y);
            *(uint2*)(ytab + g0 * 64 + o0) = p;
        }
        if (g0 + 1 < nrows) {
            *(float4*)(z + (g0 + 1) * 64 + o0) = make_float4(z1xy.x, z1xy.y, z1zw.x, z1zw.y);
            uint2 p;
            ((__half2*)&p)[0] = __floats2half2_rn(y1xy.x, y1xy.y);
            ((__half2*)&p)[1] = __floats2half2_rn(y1zw.x, y1zw.y);
            *(uint2*)(ytab + (g0 + 1) * 64 + o0) = p;
        }
        __syncthreads();   // rs reused next tile
    }
}

// ---------------------------------------------------------------------------
__device__ __forceinline__ void acc8(float* a, uint4 v) {
    float2 f;
    f = __half22float2(*(__half2*)&v.x); a[0] += f.x; a[1] += f.y;
    f = __half22float2(*(__half2*)&v.y); a[2] += f.x; a[3] += f.y;
    f = __half22float2(*(__half2*)&v.z); a[4] += f.x; a[5] += f.y;
    f = __half22float2(*(__half2*)&v.w); a[6] += f.x; a[7] += f.y;
}
// Pairwise fp16 add of two neighbor row fragments (4 HADD2).
__device__ __forceinline__ uint4 hadd4(uint4 a, uint4 b) {
    uint4 r;
    *(__half2*)&r.x = __hadd2(*(const __half2*)&a.x, *(const __half2*)&b.x);
    *(__half2*)&r.y = __hadd2(*(const __half2*)&a.y, *(const __half2*)&b.y);
    *(__half2*)&r.z = __hadd2(*(const __half2*)&a.z, *(const __half2*)&b.z);
    *(__half2*)&r.w = __hadd2(*(const __half2*)&a.w, *(const __half2*)&b.w);
    return r;
}
__device__ __forceinline__ void proc8(float* a, const uint4* __restrict__ y4,
                                      int4 na, int4 nb, int lane) {
    uint4 v0 = __ldg(y4 + na.x * 8 + lane);
    uint4 v1 = __ldg(y4 + na.y * 8 + lane);
    uint4 v2 = __ldg(y4 + na.z * 8 + lane);
    uint4 v3 = __ldg(y4 + na.w * 8 + lane);
    uint4 v4 = __ldg(y4 + nb.x * 8 + lane);
    uint4 v5 = __ldg(y4 + nb.y * 8 + lane);
    uint4 v6 = __ldg(y4 + nb.z * 8 + lane);
    uint4 v7 = __ldg(y4 + nb.w * 8 + lane);
    acc8(a, hadd4(v0, v1)); acc8(a, hadd4(v2, v3));
    acc8(a, hadd4(v4, v5)); acc8(a, hadd4(v6, v7));
}

// Gather-mean of fp16 y rows + z + optional relu -> x_new (fp32).
// 8 lanes per node, 8 rows/iter, software-pipelined index prefetch.
__global__ void __launch_bounds__(256, 6)
k_gather_add(int xm_out, int xu_out, int M, int U, int do_relu) {
    int t = blockIdx.x * blockDim.x + threadIdx.x;
    int node = t >> 3;
    if (node >= M + U) return;
    int lane = t & 7;
    bool is_movie = node < M;
    int local = is_movie ? node : node - M;
    const int pad = is_movie ? PAD_M : PAD_U;
    const int* bk = (is_movie ? g_bucket_m : g_bucket_u) + (long)local * pad;
    int dt = g_deg[(is_movie ? UQ : 0) + local];
    float iv = 1.f / fmaxf((float)dt, 1.f);
    int d = min(dt, pad);
    const uint4* y4 = (const uint4*)(is_movie ? g_hyu : g_hym);  // gather OTHER side's y

    float a[8] = {0.f, 0.f, 0.f, 0.f, 0.f, 0.f, 0.f, 0.f};
    int i = 0;
    if (d >= 8) {
        int4 na = __ldg((const int4*)(bk));
        int4 nb = __ldg((const int4*)(bk + 4));
        for (; i + 16 <= d; i += 8) {
            int4 pa = __ldg((const int4*)(bk + i + 8));    // prefetch next chunk
            int4 pb = __ldg((const int4*)(bk + i + 12));
            proc8(a, y4, na, nb, lane);
            na = pa; nb = pb;
        }
        proc8(a, y4, na, nb, lane);                        // drain pipelined chunk
        i += 8;
    }
    for (; i + 4 <= d; i += 4) {
        int4 na = __ldg((const int4*)(bk + i));
        uint4 v0 = __ldg(y4 + na.x * 8 + lane);
        uint4 v1 = __ldg(y4 + na.y * 8 + lane);
        uint4 v2 = __ldg(y4 + na.z * 8 + lane);
        uint4 v3 = __ldg(y4 + na.w * 8 + lane);
        acc8(a, hadd4(v0, v1)); acc8(a, hadd4(v2, v3));
    }
    for (; i < d; i++) {
        int nb = __ldg(bk + i);
        acc8(a, __ldg(y4 + nb * 8 + lane));
    }
    const float4* zp = (const float4*)(g_buf + (is_movie ? OFF_ZM : OFF_ZU)) + local * 16 + lane * 2;
    float4 z0 = __ldg(zp), z1 = __ldg(zp + 1);
    float4 r0 = make_float4(fmaf(a[0], iv, z0.x), fmaf(a[1], iv, z0.y),
                            fmaf(a[2], iv, z0.z), fmaf(a[3], iv, z0.w));
    float4 r1 = make_float4(fmaf(a[4], iv, z1.x), fmaf(a[5], iv, z1.y),
                            fmaf(a[6], iv, z1.z), fmaf(a[7], iv, z1.w));
    if (do_relu) {
        r0.x = fmaxf(r0.x, 0.f); r0.y = fmaxf(r0.y, 0.f);
        r0.z = fmaxf(r0.z, 0.f); r0.w = fmaxf(r0.w, 0.f);
        r1.x = fmaxf(r1.x, 0.f); r1.y = fmaxf(r1.y, 0.f);
        r1.z = fmaxf(r1.z, 0.f); r1.w = fmaxf(r1.w, 0.f);
    }
    float4* o4 = (float4*)(g_buf + (is_movie ? xm_out : xu_out)) + local * 16 + lane * 2;
    o4[0] = r0;
    o4[1] = r1;
}

// out[l] = dot(x_u[label_src[l]], x_m[label_dst[l]]); 8 lanes per label.
__global__ void k_labels(const int* __restrict__ ls, const int* __restrict__ ld,
                         int xu_off, int xm_off, float* __restrict__ out, int L) {
    int t = blockIdx.x * blockDim.x + threadIdx.x;
    int l = t >> 3;
    if (l >= L) return;
    int lane = t & 7;
    const float4* xu = (const float4*)(g_buf + xu_off);
    const float4* xm = (const float4*)(g_buf + xm_off);
    int s = __ldg(ls + l), d = __ldg(ld + l);
    float4 a0 = __ldg(xu + s * 16 + lane * 2);
    float4 a1 = __ldg(xu + s * 16 + lane * 2 + 1);
    float4 b0 = __ldg(xm + d * 16 + lane * 2);
    float4 b1 = __ldg(xm + d * 16 + lane * 2 + 1);
    float v = a0.x * b0.x;
    v = fmaf(a0.y, b0.y, v); v = fmaf(a0.z, b0.z, v); v = fmaf(a0.w, b0.w, v);
    v = fmaf(a1.x, b1.x, v); v = fmaf(a1.y, b1.y, v);
    v = fmaf(a1.z, b1.z, v); v = fmaf(a1.w, b1.w, v);
    v += __shfl_xor_sync(0xffffffffu, v, 4);
    v += __shfl_xor_sync(0xffffffffu, v, 2);
    v += __shfl_xor_sync(0xffffffffu, v, 1);
    if (lane == 0) out[l] = v;
}

// ---------------------------------------------------------------------------
extern "C" void kernel_launch(void* const* d_in, const int* in_sizes, int n_in,
                              void* d_out, int out_size) {
    const float* movie_x   = (const float*)d_in[0];
    const float* user_emb  = (const float*)d_in[1];
    const float* movie_emb = (const float*)d_in[2];
    const float* mw        = (const float*)d_in[3];
    const float* mb        = (const float*)d_in[4];
    const float* wl        = (const float*)d_in[5];
    const float* blb       = (const float*)d_in[6];
    const float* wr        = (const float*)d_in[7];
    const int*   es        = (const int*)d_in[8];
    const int*   ed        = (const int*)d_in[9];
    const int*   ls        = (const int*)d_in[10];
    const int*   ld        = (const int*)d_in[11];
    float* out = (float*)d_out;

    const int U = in_sizes[1] / HH;
    const int M = in_sizes[2] / HH;
    const int E = in_sizes[8];
    const int L = in_sizes[10];
    const int TB = 256;

    // launch 1: fused feature init (movies projected, users copied, deg zeroed)
    const int MB4 = (M + 3) / 4;
    const int UBc = (U * 16 + TB - 1) / TB;
    const int ZB  = (U + M + TB - 1) / TB;
    k_init<<<MB4 + UBc + ZB, TB>>>((const float4*)user_emb, movie_x, mw, mb, movie_emb,
                                   MB4, UBc, M, U);
    // launch 2: adjacency buckets (+degree counting)
    k_fill<<<(E + TB - 1) / TB, TB>>>(es, ed, E);

    const int GAB = (int)(((long)(M + U) * 8 + TB - 1) / TB);
    for (int layer = 0; layer < 2; layer++) {
        const int xu_in  = layer ? OFF_XU1 : OFF_XU0;
        const int xm_in  = layer ? OFF_XM1 : OFF_XM0;
        const int xu_out = layer ? OFF_XU0 : OFF_XU1;
        const int xm_out = layer ? OFF_XM0 : OFF_XM1;

        // launch 3/5: dense pre-transform y,z (persistent tiles)
        k_pre<<<GM_BLOCKS + GU_BLOCKS, 256>>>(xm_in, xu_in, wl, blb, wr, layer, M, U);
        // launch 4/6: gather-mean(y) + z (+relu) — profiled slot
        k_gather_add<<<GAB, TB>>>(xm_out, xu_out, M, U, layer == 0);
    }

    // final features are in the *0 buffers
    long lt = (long)L * 8;
    k_labels<<<(int)((lt + TB - 1) / TB), TB>>>(ls, ld, OFF_XU0, OFF_XM0, out, L);
}

// round 17
// speedup vs baseline: 1.0607x; 1.0053x over previous
#include <cuda_runtime.h>
#include <cuda_fp16.h>

// Problem constants (shapes fixed by the dataset)
#define UQ 100000          // users
#define MQ 50000           // movies
#define HH 64              // hidden dim
#define UN (UQ*HH)
#define MN (MQ*HH)
#define PAD_U 64           // max user degree slots (Poisson(20) tail safe)
#define PAD_M 128          // max movie degree slots (Poisson(40) tail safe)

// Scratch layout inside one big __device__ buffer (offsets in floats)
#define OFF_XU0  0
#define OFF_XU1  (OFF_XU0 + UN)
#define OFF_XM0  (OFF_XU1 + UN)
#define OFF_XM1  (OFF_XM0 + MN)
#define OFF_ZU   (OFF_XM1 + MN)      // z_u = x_u @ Wr^T + b   [U,64] fp32
#define OFF_ZM   (OFF_ZU + UN)       // z_m = x_m @ Wr^T + b   [M,64] fp32
#define TOTAL_F  (OFF_ZM + MN)

__device__ __align__(16) float g_buf[TOTAL_F];        // ~115 MB scratch
__device__ int g_deg[UQ + MQ];                        // users then movies (fill cursors)
__device__ __align__(16) int g_bucket_u[UQ * PAD_U];  // movie ids per user
__device__ __align__(16) int g_bucket_m[MQ * PAD_M];  // user ids per movie
__device__ __align__(16) __half g_hyu[UN];            // y_u = x_u @ Wl[l,0]^T (fp16)
__device__ __align__(16) __half g_hym[MN];            // y_m = x_m @ Wl[l,1]^T (fp16)

// ---------------------------------------------------------------------------
// Packed f32x2 helpers (Blackwell sm_103a FFMA2 path)
__device__ __forceinline__ unsigned long long pack_dup(float x) {
    unsigned long long r;
    asm("mov.b64 %0, {%1, %1};" : "=l"(r) : "f"(x));
    return r;
}
__device__ __forceinline__ unsigned long long pack2(float a, float b) {
    unsigned long long r;
    asm("mov.b64 %0, {%1, %2};" : "=l"(r) : "f"(a), "f"(b));
    return r;
}
__device__ __forceinline__ void ffma2(unsigned long long& d,
                                      unsigned long long a, unsigned long long b) {
    asm("fma.rn.f32x2 %0, %1, %2, %0;" : "+l"(d) : "l"(a), "l"(b));
}
__device__ __forceinline__ float2 unpack2(unsigned long long v) {
    float2 f;
    asm("mov.b64 {%0, %1}, %2;" : "=f"(f.x), "=f"(f.y) : "l"(v));
    return f;
}

// ---------------------------------------------------------------------------
// Fused init: movie blocks project movie_x; user blocks copy user_emb;
// tail blocks zero the degree counters (no ordering hazard: k_fill runs after).
__global__ void __launch_bounds__(256)
k_init(const float4* __restrict__ uemb,
       const float* __restrict__ mx, const float* __restrict__ w,
       const float* __restrict__ b, const float* __restrict__ memb,
       int MB4, int UBc, int M, int U) {
    int tid = threadIdx.x;
    if ((int)blockIdx.x < MB4) {
        __shared__ float xs[4][20];
        int r = tid >> 6, o = tid & 63;
        int row = blockIdx.x * 4 + r;
        if (tid < 80) {
            int rr = tid / 20, cc = tid % 20;
            int g = blockIdx.x * 4 + rr;
            if (g < M) xs[rr][cc] = __ldg(mx + g * 20 + cc);
        }
        __syncthreads();
        if (row < M) {
            float acc = __ldg(b + o) + __ldg(memb + row * 64 + o);
#pragma unroll
            for (int k = 0; k < 20; k++) acc = fmaf(xs[r][k], __ldg(w + o * 20 + k), acc);
            g_buf[OFF_XM0 + row * 64 + o] = acc;
        }
    } else if ((int)blockIdx.x < MB4 + UBc) {
        int i = ((int)blockIdx.x - MB4) * 256 + tid;
        if (i < U * 16) ((float4*)(g_buf + OFF_XU0))[i] = __ldg(uemb + i);
    } else {
        int i = ((int)blockIdx.x - MB4 - UBc) * 256 + tid;
        if (i < U + M) g_deg[i] = 0;
    }
}

// Bucket fill: degree counting and slot allocation in one pass over edges.
__global__ void k_fill(const int* __restrict__ es, const int* __restrict__ ed, int E) {
    int e = blockIdx.x * blockDim.x + threadIdx.x;
    if (e >= E) return;
    int u = __ldg(es + e), m = __ldg(ed + e);
    int su = atomicAdd(&g_deg[u], 1);
    if (su < PAD_U) g_bucket_u[u * PAD_U + su] = m;
    int sm = atomicAdd(&g_deg[UQ + m], 1);
    if (sm < PAD_M) g_bucket_m[m * PAD_M + sm] = u;
}

// ---------------------------------------------------------------------------
// Pre-transform: y = x @ Wl_y^T (fp16 out), z = x @ Wr_z^T + b (fp32).
// Persistent tiles; thread = 2 rows x 4 outs. SOFTWARE-PIPELINED x-tile load:
// next tile prefetched into registers during compute, stored after the
// read-barrier — hides the per-tile L2 round-trip.
#define PROWS 32
#define WPAD 68            // fp32 row stride (floats)
#define WPADH 68           // fp16 weight row stride (halves)
#define GM_BLOCKS 296      // movie-segment blocks
#define GU_BLOCKS 592      // user-segment blocks
__global__ void __launch_bounds__(256)
k_pre(int xm_off, int xu_off, const float* __restrict__ wl,
      const float* __restrict__ bl, const float* __restrict__ wr,
      int layer, int M, int U) {
    __shared__ __half wsy[64 * WPADH];    // Wl_y transposed [i][o], fp16
    __shared__ float  wsz[64 * WPAD];     // Wr_z transposed [i][o], fp32
    __shared__ float  rs[PROWS * WPAD];   // x rows
    const bool is_movie = (int)blockIdx.x < GM_BLOCKS;
    const int et_y = is_movie ? 1 : 0;    // movie y feeds user-dst edges
    const int et_z = is_movie ? 0 : 1;
    const float* wly = wl + (layer * 2 + et_y) * 4096;
    const float* wrz = wr + (layer * 2 + et_z) * 4096;
    const float* blz = bl + (layer * 2 + et_z) * 64;
    const int nrows = is_movie ? M : U;
    const int x_off = is_movie ? xm_off : xu_off;
    const int z_off = is_movie ? OFF_ZM : OFF_ZU;
    __half* ytab    = is_movie ? g_hym : g_hyu;
    const int ntiles = (nrows + PROWS - 1) / PROWS;
    const int t0     = is_movie ? blockIdx.x : blockIdx.x - GM_BLOCKS;
    const int tstep  = is_movie ? GM_BLOCKS : GU_BLOCKS;
    int tid = threadIdx.x;

    // Load weights ONCE per block.
    for (int idx = tid; idx < 4096; idx += 256) {
        int o = idx >> 6, i = idx & 63;   // coalesced global read
        wsy[i * WPADH + o] = __float2half_rn(__ldg(wly + idx));
        wsz[i * WPAD + o]  = __ldg(wrz + idx);
    }
    int og = tid & 15, rg = tid >> 4;     // 16 o-groups x 16 row-groups
    int o0 = og * 4, r0 = rg * 2;
    float4 bz = *(const float4*)(blz + o0);
    const unsigned long long zb_a = pack2(bz.x, bz.y), zb_b = pack2(bz.z, bz.w);
    const float4* x4 = (const float4*)(g_buf + x_off);
    float* z = g_buf + z_off;
    int ldr = tid >> 4, ldq = tid & 15;   // each thread loads rows ldr, ldr+16
    __syncthreads();

    int t = t0;
    if (t < ntiles) {
        // preload first tile
        {
            int g0 = t * PROWS + ldr, g1 = g0 + 16;
            if (g0 < nrows) *(float4*)&rs[ldr * WPAD + ldq * 4] = __ldg(x4 + g0 * 16 + ldq);
            if (g1 < nrows) *(float4*)&rs[(ldr + 16) * WPAD + ldq * 4] = __ldg(x4 + g1 * 16 + ldq);
        }
        __syncthreads();

        for (; t < ntiles; ) {
            const int tn = t + tstep;
            const bool hasnext = tn < ntiles;
            float4 p0, p1;
            bool v0ok = false, v1ok = false;
            if (hasnext) {                 // prefetch next tile (overlaps compute)
                int g0 = tn * PROWS + ldr, g1 = g0 + 16;
                v0ok = g0 < nrows; v1ok = g1 < nrows;
                if (v0ok) p0 = __ldg(x4 + g0 * 16 + ldq);
                if (v1ok) p1 = __ldg(x4 + g1 * 16 + ldq);
            }

            unsigned long long y0a = 0ull, y0b = 0ull, y1a = 0ull, y1b = 0ull;
            unsigned long long z0a = zb_a, z0b = zb_b, z1a = zb_a, z1b = zb_b;
#pragma unroll 16
            for (int i = 0; i < 64; i++) {
                uint2 wyh = *(const uint2*)&wsy[i * WPADH + o0];          // LDS.64
                ulonglong2 wz = *(const ulonglong2*)&wsz[i * WPAD + o0];  // LDS.128
                float2 wy01 = __half22float2(*(__half2*)&wyh.x);
                float2 wy23 = __half22float2(*(__half2*)&wyh.y);
                unsigned long long wya = pack2(wy01.x, wy01.y);
                unsigned long long wyb = pack2(wy23.x, wy23.y);
                unsigned long long px0 = pack_dup(rs[r0 * WPAD + i]);
                unsigned long long px1 = pack_dup(rs[(r0 + 1) * WPAD + i]);
                ffma2(y0a, px0, wya); ffma2(y0b, px0, wyb);
                ffma2(z0a, px0, wz.x); ffma2(z0b, px0, wz.y);
                ffma2(y1a, px1, wya); ffma2(y1b, px1, wyb);
                ffma2(z1a, px1, wz.x); ffma2(z1b, px1, wz.y);
            }
            __syncthreads();               // everyone done READING rs
            if (v0ok) *(float4*)&rs[ldr * WPAD + ldq * 4] = p0;
            if (v1ok) *(float4*)&rs[(ldr + 16) * WPAD + ldq * 4] = p1;

            // write outputs of tile t
            float2 y0xy = unpack2(y0a), y0zw = unpack2(y0b);
            float2 y1xy = unpack2(y1a), y1zw = unpack2(y1b);
            float2 z0xy = unpack2(z0a), z0zw = unpack2(z0b);
            float2 z1xy = unpack2(z1a), z1zw = unpack2(z1b);
            int g0 = t * PROWS + r0;
            if (g0 < nrows) {
                *(float4*)(z + g0 * 64 + o0) = make_float4(z0xy.x, z0xy.y, z0zw.x, z0zw.y);
                uint2 p;
                ((__half2*)&p)[0] = __floats2half2_rn(y0xy.x, y0xy.y);
                ((__half2*)&p)[1] = __floats2half2_rn(y0zw.x, y0zw.y);
                *(uint2*)(ytab + g0 * 64 + o0) = p;
            }
            if (g0 + 1 < nrows) {
                *(float4*)(z + (g0 + 1) * 64 + o0) = make_float4(z1xy.x, z1xy.y, z1zw.x, z1zw.y);
                uint2 p;
                ((__half2*)&p)[0] = __floats2half2_rn(y1xy.x, y1xy.y);
                ((__half2*)&p)[1] = __floats2half2_rn(y1zw.x, y1zw.y);
                *(uint2*)(ytab + (g0 + 1) * 64 + o0) = p;
            }
            __syncthreads();               // rs ready for next tile
            t = tn;
        }
    }
}

// ---------------------------------------------------------------------------
__device__ __forceinline__ void acc8(float* a, uint4 v) {
    float2 f;
    f = __half22float2(*(__half2*)&v.x); a[0] += f.x; a[1] += f.y;
    f = __half22float2(*(__half2*)&v.y); a[2] += f.x; a[3] += f.y;
    f = __half22float2(*(__half2*)&v.z); a[4] += f.x; a[5] += f.y;
    f = __half22float2(*(__half2*)&v.w); a[6] += f.x; a[7] += f.y;
}
// Pairwise fp16 add of two neighbor row fragments (4 HADD2).
__device__ __forceinline__ uint4 hadd4(uint4 a, uint4 b) {
    uint4 r;
    *(__half2*)&r.x = __hadd2(*(const __half2*)&a.x, *(const __half2*)&b.x);
    *(__half2*)&r.y = __hadd2(*(const __half2*)&a.y, *(const __half2*)&b.y);
    *(__half2*)&r.z = __hadd2(*(const __half2*)&a.z, *(const __half2*)&b.z);
    *(__half2*)&r.w = __hadd2(*(const __half2*)&a.w, *(const __half2*)&b.w);
    return r;
}
// Depth-2 fp16 tree over 8 rows (6 hadd4) + 2 fp32 accumulates.
__device__ __forceinline__ void proc8(float* a, const uint4* __restrict__ y4,
                                      int4 na, int4 nb, int lane) {
    uint4 v0 = __ldg(y4 + na.x * 8 + lane);
    uint4 v1 = __ldg(y4 + na.y * 8 + lane);
    uint4 v2 = __ldg(y4 + na.z * 8 + lane);
    uint4 v3 = __ldg(y4 + na.w * 8 + lane);
    uint4 v4 = __ldg(y4 + nb.x * 8 + lane);
    uint4 v5 = __ldg(y4 + nb.y * 8 + lane);
    uint4 v6 = __ldg(y4 + nb.z * 8 + lane);
    uint4 v7 = __ldg(y4 + nb.w * 8 + lane);
    acc8(a, hadd4(hadd4(v0, v1), hadd4(v2, v3)));
    acc8(a, hadd4(hadd4(v4, v5), hadd4(v6, v7)));
}

// Gather-mean of fp16 y rows + z + optional relu -> x_new (fp32).
// 8 lanes per node, 8 rows/iter, software-pipelined index prefetch,
// depth-2 fp16 pre-add tree.
__global__ void __launch_bounds__(256, 6)
k_gather_add(int xm_out, int xu_out, int M, int U, int do_relu) {
    int t = blockIdx.x * blockDim.x + threadIdx.x;
    int node = t >> 3;
    if (node >= M + U) return;
    int lane = t & 7;
    bool is_movie = node < M;
    int local = is_movie ? node : node - M;
    const int pad = is_movie ? PAD_M : PAD_U;
    const int* bk = (is_movie ? g_bucket_m : g_bucket_u) + (long)local * pad;
    int dt = g_deg[(is_movie ? UQ : 0) + local];
    float iv = 1.f / fmaxf((float)dt, 1.f);
    int d = min(dt, pad);
    const uint4* y4 = (const uint4*)(is_movie ? g_hyu : g_hym);  // gather OTHER side's y

    float a[8] = {0.f, 0.f, 0.f, 0.f, 0.f, 0.f, 0.f, 0.f};
    int i = 0;
    if (d >= 8) {
        int4 na = __ldg((const int4*)(bk));
        int4 nb = __ldg((const int4*)(bk + 4));
        for (; i + 16 <= d; i += 8) {
            int4 pa = __ldg((const int4*)(bk + i + 8));    // prefetch next chunk
            int4 pb = __ldg((const int4*)(bk + i + 12));
            proc8(a, y4, na, nb, lane);
            na = pa; nb = pb;
        }
        proc8(a, y4, na, nb, lane);                        // drain pipelined chunk
        i += 8;
    }
    for (; i + 4 <= d; i += 4) {
        int4 na = __ldg((const int4*)(bk + i));
        uint4 v0 = __ldg(y4 + na.x * 8 + lane);
        uint4 v1 = __ldg(y4 + na.y * 8 + lane);
        uint4 v2 = __ldg(y4 + na.z * 8 + lane);
        uint4 v3 = __ldg(y4 + na.w * 8 + lane);
        acc8(a, hadd4(hadd4(v0, v1), hadd4(v2, v3)));
    }
    for (; i < d; i++) {
        int nb = __ldg(bk + i);
        acc8(a, __ldg(y4 + nb * 8 + lane));
    }
    const float4* zp = (const float4*)(g_buf + (is_movie ? OFF_ZM : OFF_ZU)) + local * 16 + lane * 2;
    float4 z0 = __ldg(zp), z1 = __ldg(zp + 1);
    float4 r0 = make_float4(fmaf(a[0], iv, z0.x), fmaf(a[1], iv, z0.y),
                            fmaf(a[2], iv, z0.z), fmaf(a[3], iv, z0.w));
    float4 r1 = make_float4(fmaf(a[4], iv, z1.x), fmaf(a[5], iv, z1.y),
                            fmaf(a[6], iv, z1.z), fmaf(a[7], iv, z1.w));
    if (do_relu) {
        r0.x = fmaxf(r0.x, 0.f); r0.y = fmaxf(r0.y, 0.f);
        r0.z = fmaxf(r0.z, 0.f); r0.w = fmaxf(r0.w, 0.f);
        r1.x = fmaxf(r1.x, 0.f); r1.y = fmaxf(r1.y, 0.f);
        r1.z = fmaxf(r1.z, 0.f); r1.w = fmaxf(r1.w, 0.f);
    }
    float4* o4 = (float4*)(g_buf + (is_movie ? xm_out : xu_out)) + local * 16 + lane * 2;
    o4[0] = r0;
    o4[1] = r1;
}

// out[l] = dot(x_u[label_src[l]], x_m[label_dst[l]]); 8 lanes per label.
__global__ void k_labels(const int* __restrict__ ls, const int* __restrict__ ld,
                         int xu_off, int xm_off, float* __restrict__ out, int L) {
    int t = blockIdx.x * blockDim.x + threadIdx.x;
    int l = t >> 3;
    if (l >= L) return;
    int lane = t & 7;
    const float4* xu = (const float4*)(g_buf + xu_off);
    const float4* xm = (const float4*)(g_buf + xm_off);
    int s = __ldg(ls + l), d = __ldg(ld + l);
    float4 a0 = __ldg(xu + s * 16 + lane * 2);
    float4 a1 = __ldg(xu + s * 16 + lane * 2 + 1);
    float4 b0 = __ldg(xm + d * 16 + lane * 2);
    float4 b1 = __ldg(xm + d * 16 + lane * 2 + 1);
    float v = a0.x * b0.x;
    v = fmaf(a0.y, b0.y, v); v = fmaf(a0.z, b0.z, v); v = fmaf(a0.w, b0.w, v);
    v = fmaf(a1.x, b1.x, v); v = fmaf(a1.y, b1.y, v);
    v = fmaf(a1.z, b1.z, v); v = fmaf(a1.w, b1.w, v);
    v += __shfl_xor_sync(0xffffffffu, v, 4);
    v += __shfl_xor_sync(0xffffffffu, v, 2);
    v += __shfl_xor_sync(0xffffffffu, v, 1);
    if (lane == 0) out[l] = v;
}

// ---------------------------------------------------------------------------
extern "C" void kernel_launch(void* const* d_in, const int* in_sizes, int n_in,
                              void* d_out, int out_size) {
    const float* movie_x   = (const float*)d_in[0];
    const float* user_emb  = (const float*)d_in[1];
    const float* movie_emb = (const float*)d_in[2];
    const float* mw        = (const float*)d_in[3];
    const float* mb        = (const float*)d_in[4];
    const float* wl        = (const float*)d_in[5];
    const float* blb       = (const float*)d_in[6];
    const float* wr        = (const float*)d_in[7];
    const int*   es        = (const int*)d_in[8];
    const int*   ed        = (const int*)d_in[9];
    const int*   ls        = (const int*)d_in[10];
    const int*   ld        = (const int*)d_in[11];
    float* out = (float*)d_out;

    const int U = in_sizes[1] / HH;
    const int M = in_sizes[2] / HH;
    const int E = in_sizes[8];
    const int L = in_sizes[10];
    const int TB = 256;

    // launch 1: fused feature init (movies projected, users copied, deg zeroed)
    const int MB4 = (M + 3) / 4;
    const int UBc = (U * 16 + TB - 1) / TB;
    const int ZB  = (U + M + TB - 1) / TB;
    k_init<<<MB4 + UBc + ZB, TB>>>((const float4*)user_emb, movie_x, mw, mb, movie_emb,
                                   MB4, UBc, M, U);
    // launch 2: adjacency buckets (+degree counting)
    k_fill<<<(E + TB - 1) / TB, TB>>>(es, ed, E);

    const int GAB = (int)(((long)(M + U) * 8 + TB - 1) / TB);
    for (int layer = 0; layer < 2; layer++) {
        const int xu_in  = layer ? OFF_XU1 : OFF_XU0;
        const int xm_in  = layer ? OFF_XM1 : OFF_XM0;
        const int xu_out = layer ? OFF_XU0 : OFF_XU1;
        const int xm_out = layer ? OFF_XM0 : OFF_XM1;

        // launch 3/5: dense pre-transform y,z (persistent tiles, pipelined)
        k_pre<<<GM_BLOCKS + GU_BLOCKS, 256>>>(xm_in, xu_in, wl, blb, wr, layer, M, U);
        // launch 4/6: gather-mean(y) + z (+relu) — profiled slot
        k_gather_add<<<GAB, TB>>>(xm_out, xu_out, M, U, layer == 0);
    }

    // final features are in the *0 buffers
    long lt = (long)L * 8;
    k_labels<<<(int)((lt + TB - 1) / TB), TB>>>(ls, ld, OFF_XU0, OFF_XM0, out, L);
}